// round 2
// baseline (speedup 1.0000x reference)
#include <cuda_runtime.h>
#include <math.h>

// ---------------------------------------------------------------------------
// SelfAttention: hidden[4,2048,1024] fp32, W_qkv[1024,3072] fp32
//   qkv = hidden @ W                      (M=8192, N=3072, K=1024)
//   scores[b] = Q[b] @ K[b]^T * 1/32      (M=2048, N=2048, K=1024, per batch)
//   P = softmax_rows(scores)
//   out[b] = P[b] @ V[b]                  (M=2048, N=1024, K=2048, per batch)
// Scratch lives in __device__ globals (no allocation allowed).
// ---------------------------------------------------------------------------

#define BATCH 4
#define SEQ   2048
#define EMB   1024
#define BS    (BATCH * SEQ)      // 8192

__device__ float g_qkv[(long)BS * (3 * EMB)];          // [8192, 3072]
__device__ float g_scores[(long)BATCH * SEQ * SEQ];    // [4, 2048, 2048]

#define BM 128
#define BN 128
#define BK 8
#define TM 8
#define TN 8

// C[M,N] = alpha * A[M,K] @ op(B),  op(B)=B[K,N] (NN) or B[N,K]^T (NT).
// All dims assumed divisible by tile sizes; all pointers 16B aligned.
template <bool TRANSB>
__global__ __launch_bounds__(256, 2)
void sgemm_kernel(const float* __restrict__ A, int lda, long strideA,
                  const float* __restrict__ B, int ldb, long strideB,
                  float* __restrict__ C, int ldc, long strideC,
                  int M, int N, int K, float alpha)
{
    __shared__ float As[BK][BM];
    __shared__ float Bs[BK][BN];

    const int b = blockIdx.z;
    A += (long)b * strideA;
    B += (long)b * strideB;
    C += (long)b * strideC;

    const int row0 = blockIdx.y * BM;
    const int col0 = blockIdx.x * BN;

    const int tid = threadIdx.x;
    const int tx = tid & 15;         // 0..15 -> 8 cols each
    const int ty = tid >> 4;         // 0..15 -> 8 rows each

    // A-tile load mapping: 128 rows x 8 cols, 1 float4 per thread
    const int aRow  = tid >> 1;              // 0..127
    const int aPart = (tid & 1) << 2;        // 0 or 4
    // B-tile NN mapping: 8 rows x 128 cols
    const int bRowNN = tid >> 5;             // 0..7
    const int bColNN = (tid & 31) << 2;      // 0..124
    // B-tile NT mapping: 128 N-rows x 8 K-cols
    const int bN_NT   = tid >> 1;            // 0..127
    const int bPartNT = (tid & 1) << 2;      // 0 or 4

    float acc[TM][TN];
    #pragma unroll
    for (int i = 0; i < TM; i++)
        #pragma unroll
        for (int j = 0; j < TN; j++)
            acc[i][j] = 0.0f;

    for (int k0 = 0; k0 < K; k0 += BK) {
        // --- load A tile (transposed into As[k][m]) ---
        float4 av = *reinterpret_cast<const float4*>(
            A + (long)(row0 + aRow) * lda + k0 + aPart);
        As[aPart + 0][aRow] = av.x;
        As[aPart + 1][aRow] = av.y;
        As[aPart + 2][aRow] = av.z;
        As[aPart + 3][aRow] = av.w;

        // --- load B tile into Bs[k][n] ---
        if (TRANSB) {
            float4 bv = *reinterpret_cast<const float4*>(
                B + (long)(col0 + bN_NT) * ldb + k0 + bPartNT);
            Bs[bPartNT + 0][bN_NT] = bv.x;
            Bs[bPartNT + 1][bN_NT] = bv.y;
            Bs[bPartNT + 2][bN_NT] = bv.z;
            Bs[bPartNT + 3][bN_NT] = bv.w;
        } else {
            float4 bv = *reinterpret_cast<const float4*>(
                B + (long)(k0 + bRowNN) * ldb + col0 + bColNN);
            *reinterpret_cast<float4*>(&Bs[bRowNN][bColNN]) = bv;
        }
        __syncthreads();

        #pragma unroll
        for (int kk = 0; kk < BK; kk++) {
            float ra[TM], rb[TN];
            float4 a0 = *reinterpret_cast<const float4*>(&As[kk][ty * TM]);
            float4 a1 = *reinterpret_cast<const float4*>(&As[kk][ty * TM + 4]);
            ra[0]=a0.x; ra[1]=a0.y; ra[2]=a0.z; ra[3]=a0.w;
            ra[4]=a1.x; ra[5]=a1.y; ra[6]=a1.z; ra[7]=a1.w;
            float4 b0 = *reinterpret_cast<const float4*>(&Bs[kk][tx * TN]);
            float4 b1 = *reinterpret_cast<const float4*>(&Bs[kk][tx * TN + 4]);
            rb[0]=b0.x; rb[1]=b0.y; rb[2]=b0.z; rb[3]=b0.w;
            rb[4]=b1.x; rb[5]=b1.y; rb[6]=b1.z; rb[7]=b1.w;
            #pragma unroll
            for (int i = 0; i < TM; i++)
                #pragma unroll
                for (int j = 0; j < TN; j++)
                    acc[i][j] = fmaf(ra[i], rb[j], acc[i][j]);
        }
        __syncthreads();
    }

    // --- epilogue ---
    #pragma unroll
    for (int i = 0; i < TM; i++) {
        long crow = (long)(row0 + ty * TM + i) * ldc + col0 + tx * TN;
        float4 o0 = make_float4(acc[i][0]*alpha, acc[i][1]*alpha,
                                acc[i][2]*alpha, acc[i][3]*alpha);
        float4 o1 = make_float4(acc[i][4]*alpha, acc[i][5]*alpha,
                                acc[i][6]*alpha, acc[i][7]*alpha);
        *reinterpret_cast<float4*>(C + crow)     = o0;
        *reinterpret_cast<float4*>(C + crow + 4) = o1;
    }
}

// Rowwise softmax over rows of length S. One block (256 threads) per row.
__global__ __launch_bounds__(256)
void softmax_kernel(float* __restrict__ scores, int S)
{
    const long row = blockIdx.x;
    float* r = scores + row * (long)S;
    const int tid = threadIdx.x;

    __shared__ float red[256];

    // 1) max
    float m = -INFINITY;
    for (int i = tid; i < S; i += 256) m = fmaxf(m, r[i]);
    red[tid] = m;
    __syncthreads();
    for (int s = 128; s > 0; s >>= 1) {
        if (tid < s) red[tid] = fmaxf(red[tid], red[tid + s]);
        __syncthreads();
    }
    const float rowmax = red[0];
    __syncthreads();

    // 2) exp + sum
    float sum = 0.0f;
    for (int i = tid; i < S; i += 256) {
        float e = expf(r[i] - rowmax);
        r[i] = e;
        sum += e;
    }
    red[tid] = sum;
    __syncthreads();
    for (int s = 128; s > 0; s >>= 1) {
        if (tid < s) red[tid] += red[tid + s];
        __syncthreads();
    }
    const float inv = 1.0f / red[0];
    __syncthreads();

    // 3) normalize
    for (int i = tid; i < S; i += 256) r[i] *= inv;
}

extern "C" void kernel_launch(void* const* d_in, const int* in_sizes, int n_in,
                              void* d_out, int out_size)
{
    const float* hidden = (const float*)d_in[0];   // [4,2048,1024]
    const float* W      = (const float*)d_in[1];   // [1024,3072]
    float* out          = (float*)d_out;           // [4,2048,1024]

    float* qkv = nullptr;
    float* scores = nullptr;
    cudaGetSymbolAddress((void**)&qkv, g_qkv);
    cudaGetSymbolAddress((void**)&scores, g_scores);

    const float scale = 1.0f / 32.0f;  // 1/sqrt(1024)

    // 1) qkv = hidden @ W      M=8192, N=3072, K=1024 (NN)
    {
        dim3 grid(3 * EMB / BN, BS / BM, 1);
        sgemm_kernel<false><<<grid, 256>>>(
            hidden, EMB, 0,
            W, 3 * EMB, 0,
            qkv, 3 * EMB, 0,
            BS, 3 * EMB, EMB, 1.0f);
    }

    // 2) scores[b] = Q[b] @ K[b]^T * scale   M=N=2048, K=1024 (NT), per batch
    {
        dim3 grid(SEQ / BN, SEQ / BM, BATCH);
        sgemm_kernel<true><<<grid, 256>>>(
            qkv + 0,   3 * EMB, (long)SEQ * 3 * EMB,
            qkv + EMB, 3 * EMB, (long)SEQ * 3 * EMB,
            scores, SEQ, (long)SEQ * SEQ,
            SEQ, SEQ, EMB, scale);
    }

    // 3) softmax rows
    softmax_kernel<<<BATCH * SEQ, 256>>>(scores, SEQ);

    // 4) out[b] = P[b] @ V[b]   M=2048, N=1024, K=2048 (NN), per batch
    {
        dim3 grid(EMB / BN, SEQ / BM, BATCH);
        sgemm_kernel<false><<<grid, 256>>>(
            scores, SEQ, (long)SEQ * SEQ,
            qkv + 2 * EMB, 3 * EMB, (long)SEQ * 3 * EMB,
            out, EMB, (long)SEQ * EMB,
            SEQ, EMB, SEQ, 1.0f);
    }
}

// round 4
// speedup vs baseline: 2.6501x; 2.6501x over previous
#include <cuda_runtime.h>
#include <cuda_fp16.h>
#include <cstdint>
#include <math.h>

// ---------------------------------------------------------------------------
// SelfAttention via legacy tensor path (mma.sync HMMA, fp32-accurate fp16
// hi/lo split: A@B = Ahi@Bhi + Ahi@Blo + Alo@Bhi, fp32 accumulate):
//   qkv = hidden @ W                      (M=8192, N=3072, K=1024)
//   Kt  = transpose(K section of qkv)     ([B,E,S])
//   scores[b] = Q[b] @ K[b]^T * 1/32      (M=2048, N=2048, K=1024)
//   P = softmax_rows(scores)
//   out[b] = P[b] @ V[b]                  (M=2048, N=1024, K=2048)
// All B operands are [K,N] row-major in gmem -> one GEMM kernel, no transposes
// inside the GEMM.
// ---------------------------------------------------------------------------

#define BATCH 4
#define SEQ   2048
#define EMB   1024
#define BS    8192

__device__ float g_qkv[(long)BS * 3 * EMB];          // [8192, 3072]
__device__ float g_scores[(long)BATCH * SEQ * SEQ];  // [4, 2048, 2048]
__device__ float g_kt[(long)BATCH * EMB * SEQ];      // [4, 1024, 2048]

// ---------------- helpers ----------------
__device__ __forceinline__ uint32_t smem_u32(const void* p) {
    uint32_t a;
    asm("{ .reg .u64 t; cvta.to.shared.u64 t, %1; cvt.u32.u64 %0, t; }"
        : "=r"(a) : "l"(p));
    return a;
}

#define LDSM_X4(r, a)                                                        \
    asm volatile("ldmatrix.sync.aligned.m8n8.x4.shared.b16 {%0,%1,%2,%3}, [%4];" \
                 : "=r"((r)[0]), "=r"((r)[1]), "=r"((r)[2]), "=r"((r)[3])    \
                 : "r"(a))

#define LDSM_X4_T(r0, r1, r2, r3, a)                                         \
    asm volatile("ldmatrix.sync.aligned.m8n8.x4.trans.shared.b16 {%0,%1,%2,%3}, [%4];" \
                 : "=r"(r0), "=r"(r1), "=r"(r2), "=r"(r3)                    \
                 : "r"(a))

__device__ __forceinline__ void mma16816(float* c, const uint32_t* a, const uint32_t* b) {
    asm volatile(
        "mma.sync.aligned.m16n8k16.row.col.f32.f16.f16.f32 "
        "{%0,%1,%2,%3}, {%4,%5,%6,%7}, {%8,%9}, {%0,%1,%2,%3};"
        : "+f"(c[0]), "+f"(c[1]), "+f"(c[2]), "+f"(c[3])
        : "r"(a[0]), "r"(a[1]), "r"(a[2]), "r"(a[3]), "r"(b[0]), "r"(b[1]));
}

// split fp32x4 -> hi/lo fp16x4 packed as 2x b32 each
__device__ __forceinline__ void split4(float4 v, uint32_t* h, uint32_t* l) {
    __half h0 = __float2half_rn(v.x), h1 = __float2half_rn(v.y);
    __half h2 = __float2half_rn(v.z), h3 = __float2half_rn(v.w);
    __half l0 = __float2half_rn(v.x - __half2float(h0));
    __half l1 = __float2half_rn(v.y - __half2float(h1));
    __half l2 = __float2half_rn(v.z - __half2float(h2));
    __half l3 = __float2half_rn(v.w - __half2float(h3));
    __half2 ha = __halves2half2(h0, h1), hb = __halves2half2(h2, h3);
    __half2 la = __halves2half2(l0, l1), lb = __halves2half2(l2, l3);
    h[0] = *(uint32_t*)&ha; h[1] = *(uint32_t*)&hb;
    l[0] = *(uint32_t*)&la; l[1] = *(uint32_t*)&lb;
}

__device__ __forceinline__ void sts64(uint32_t addr, uint32_t a, uint32_t b) {
    asm volatile("st.shared.v2.b32 [%0], {%1,%2};" :: "r"(addr), "r"(a), "r"(b));
}

// ---------------- GEMM ----------------
// Tile: BM=128, BN=128, BK=32 halves. 256 threads = 8 warps (2 M x 4 N),
// each warp 64x32 via 4x4 m16n8k16 tiles, fp16 hi/lo split (3 MMA per tile).
#define LDA_B   80                   // A smem row stride bytes (32h + 8h pad)
#define LDB_B   272                  // B smem row stride bytes (128h + 8h pad)
#define A_PLANE 10240                // 128 * 80
#define B_PLANE 8704                 // 32 * 272
#define STAGE   (2 * A_PLANE + 2 * B_PLANE)   // 37888
#define DSMEM   (2 * STAGE)                   // 75776

__global__ __launch_bounds__(256, 1)
void hmma_gemm(const float* __restrict__ A, int lda, long sA,
               const float* __restrict__ B, int ldb, long sB,
               float* __restrict__ C, int ldc, long sC,
               int K, float alpha)
{
    extern __shared__ char sm[];
    const uint32_t sbase = smem_u32(sm);

    const int tid = threadIdx.x;
    const int lane = tid & 31;
    const int wid = tid >> 5;

    const int bz = blockIdx.z;
    A += (long)bz * sA;
    B += (long)bz * sB;
    C += (long)bz * sC;
    const int row0 = blockIdx.y * 128;
    const int col0 = blockIdx.x * 128;

    const int mb = (wid >> 2) * 64;   // warp M offset in tile
    const int nb = (wid & 3) * 32;    // warp N offset in tile

    // loader per-thread indices
    const int aR = tid >> 3;               // + j*32
    const int aC = (tid & 7) << 2;         // 0..28
    const int bK = tid >> 5;               // + j*8
    const int bN = (tid & 31) << 2;        // 0..124

    // fragment base addresses (per-lane)
    const uint32_t aFrag = sbase + (uint32_t)((mb + (lane & 15)) * LDA_B + (lane >> 4) * 16);
    const uint32_t bFrag = sbase + 2 * A_PLANE +
        (uint32_t)(((lane & 7) + ((lane >> 3) & 1) * 8) * LDB_B + (nb + (lane >> 4) * 8) * 2);

    float acc[4][4][4];
    #pragma unroll
    for (int i = 0; i < 4; i++)
        #pragma unroll
        for (int j = 0; j < 4; j++)
            #pragma unroll
            for (int e = 0; e < 4; e++) acc[i][j][e] = 0.0f;

    const int nIter = K / 32;
    float4 aReg[4], bReg[4];

    // gmem loads for chunk k0
    auto ldg = [&](int k0) {
        #pragma unroll
        for (int j = 0; j < 4; j++)
            aReg[j] = *reinterpret_cast<const float4*>(
                A + (long)(row0 + j * 32 + aR) * lda + k0 + aC);
        #pragma unroll
        for (int j = 0; j < 4; j++)
            bReg[j] = *reinterpret_cast<const float4*>(
                B + (long)(k0 + j * 8 + bK) * ldb + col0 + bN);
    };
    // convert + store staged regs into stage st
    auto sts = [&](uint32_t st) {
        #pragma unroll
        for (int j = 0; j < 4; j++) {
            uint32_t h[2], l[2];
            split4(aReg[j], h, l);
            uint32_t ad = sbase + st + (uint32_t)((j * 32 + aR) * LDA_B + aC * 2);
            sts64(ad, h[0], h[1]);
            sts64(ad + A_PLANE, l[0], l[1]);
        }
        #pragma unroll
        for (int j = 0; j < 4; j++) {
            uint32_t h[2], l[2];
            split4(bReg[j], h, l);
            uint32_t ad = sbase + st + 2 * A_PLANE + (uint32_t)((j * 8 + bK) * LDB_B + bN * 2);
            sts64(ad, h[0], h[1]);
            sts64(ad + B_PLANE, l[0], l[1]);
        }
    };

    ldg(0);
    sts(0);
    __syncthreads();

    for (int kb = 0; kb < nIter; kb++) {
        if (kb + 1 < nIter) ldg((kb + 1) * 32);   // prefetch next chunk

        const uint32_t st = (uint32_t)(kb & 1) * STAGE;
        #pragma unroll
        for (int ks = 0; ks < 2; ks++) {
            uint32_t ah[4][4], al[4][4], bh[4][2], bl[4][2];
            #pragma unroll
            for (int i = 0; i < 4; i++) {
                uint32_t ad = aFrag + st + (uint32_t)(i * 16 * LDA_B + ks * 32);
                LDSM_X4(ah[i], ad);
                LDSM_X4(al[i], ad + A_PLANE);
            }
            #pragma unroll
            for (int j2 = 0; j2 < 2; j2++) {
                uint32_t bd = bFrag + st + (uint32_t)(ks * 16 * LDB_B + j2 * 32);
                LDSM_X4_T(bh[2 * j2][0], bh[2 * j2][1], bh[2 * j2 + 1][0], bh[2 * j2 + 1][1], bd);
                LDSM_X4_T(bl[2 * j2][0], bl[2 * j2][1], bl[2 * j2 + 1][0], bl[2 * j2 + 1][1],
                          bd + B_PLANE);
            }
            #pragma unroll
            for (int i = 0; i < 4; i++)
                #pragma unroll
                for (int j = 0; j < 4; j++) mma16816(acc[i][j], ah[i], bh[j]);
            #pragma unroll
            for (int i = 0; i < 4; i++)
                #pragma unroll
                for (int j = 0; j < 4; j++) mma16816(acc[i][j], ah[i], bl[j]);
            #pragma unroll
            for (int i = 0; i < 4; i++)
                #pragma unroll
                for (int j = 0; j < 4; j++) mma16816(acc[i][j], al[i], bh[j]);
        }

        if (kb + 1 < nIter) sts((uint32_t)((kb + 1) & 1) * STAGE);
        __syncthreads();
    }

    // epilogue
    #pragma unroll
    for (int i = 0; i < 4; i++) {
        const int r = row0 + mb + i * 16 + (lane >> 2);
        #pragma unroll
        for (int j = 0; j < 4; j++) {
            const int c = col0 + nb + j * 8 + (lane & 3) * 2;
            float2 v0 = make_float2(acc[i][j][0] * alpha, acc[i][j][1] * alpha);
            float2 v1 = make_float2(acc[i][j][2] * alpha, acc[i][j][3] * alpha);
            *reinterpret_cast<float2*>(C + (long)r * ldc + c) = v0;
            *reinterpret_cast<float2*>(C + (long)(r + 8) * ldc + c) = v1;
        }
    }
}

// ---------------- K transpose: qkv K-section [S,E] -> Kt [E,S] ----------------
__global__ __launch_bounds__(256)
void transpose_k(const float* __restrict__ qkv, float* __restrict__ kt)
{
    __shared__ float t[32][33];
    const int b = blockIdx.z;
    const int s0 = blockIdx.x * 32;
    const int e0 = blockIdx.y * 32;
    const float* Ksec = qkv + (long)b * SEQ * (3 * EMB) + EMB;
    float* Kt = kt + (long)b * EMB * SEQ;
    const int tx = threadIdx.x & 31;
    const int ty = threadIdx.x >> 5;   // 0..7
    #pragma unroll
    for (int j = 0; j < 32; j += 8)
        t[ty + j][tx] = Ksec[(long)(s0 + ty + j) * (3 * EMB) + e0 + tx];
    __syncthreads();
    #pragma unroll
    for (int j = 0; j < 32; j += 8)
        Kt[(long)(e0 + ty + j) * SEQ + s0 + tx] = t[tx][ty + j];
}

// ---------------- softmax: one row (2048) per 256-thread block ----------------
__global__ __launch_bounds__(256)
void softmax_kernel(float* __restrict__ scores)
{
    __shared__ float red[8];
    const long row = blockIdx.x;
    float4* r4 = reinterpret_cast<float4*>(scores + row * (long)SEQ);
    const int tid = threadIdx.x;
    const int wid = tid >> 5, lane = tid & 31;

    float4 a = r4[tid];
    float4 b = r4[tid + 256];

    float m = fmaxf(fmaxf(fmaxf(a.x, a.y), fmaxf(a.z, a.w)),
                    fmaxf(fmaxf(b.x, b.y), fmaxf(b.z, b.w)));
    #pragma unroll
    for (int o = 16; o; o >>= 1) m = fmaxf(m, __shfl_xor_sync(0xffffffffu, m, o));
    if (lane == 0) red[wid] = m;
    __syncthreads();
    float rowmax = red[0];
    #pragma unroll
    for (int i = 1; i < 8; i++) rowmax = fmaxf(rowmax, red[i]);
    __syncthreads();

    a.x = __expf(a.x - rowmax); a.y = __expf(a.y - rowmax);
    a.z = __expf(a.z - rowmax); a.w = __expf(a.w - rowmax);
    b.x = __expf(b.x - rowmax); b.y = __expf(b.y - rowmax);
    b.z = __expf(b.z - rowmax); b.w = __expf(b.w - rowmax);

    float s = a.x + a.y + a.z + a.w + b.x + b.y + b.z + b.w;
    #pragma unroll
    for (int o = 16; o; o >>= 1) s += __shfl_xor_sync(0xffffffffu, s, o);
    if (lane == 0) red[wid] = s;
    __syncthreads();
    float tot = red[0];
    #pragma unroll
    for (int i = 1; i < 8; i++) tot += red[i];
    const float inv = 1.0f / tot;

    a.x *= inv; a.y *= inv; a.z *= inv; a.w *= inv;
    b.x *= inv; b.y *= inv; b.z *= inv; b.w *= inv;
    r4[tid] = a;
    r4[tid + 256] = b;
}

// ---------------- launch ----------------
extern "C" void kernel_launch(void* const* d_in, const int* in_sizes, int n_in,
                              void* d_out, int out_size)
{
    const float* hidden = (const float*)d_in[0];   // [4,2048,1024]
    const float* W      = (const float*)d_in[1];   // [1024,3072]
    float* out          = (float*)d_out;           // [4,2048,1024]

    float* qkv = nullptr; float* scores = nullptr; float* kt = nullptr;
    cudaGetSymbolAddress((void**)&qkv, g_qkv);
    cudaGetSymbolAddress((void**)&scores, g_scores);
    cudaGetSymbolAddress((void**)&kt, g_kt);

    cudaFuncSetAttribute(hmma_gemm, cudaFuncAttributeMaxDynamicSharedMemorySize, DSMEM);

    // 1) qkv = hidden @ W   (M=8192, N=3072, K=1024)
    hmma_gemm<<<dim3(3 * EMB / 128, BS / 128, 1), 256, DSMEM>>>(
        hidden, EMB, 0,
        W, 3 * EMB, 0,
        qkv, 3 * EMB, 0,
        EMB, 1.0f);

    // 2) Kt[b][e][s] = K[b][s][e]
    transpose_k<<<dim3(SEQ / 32, EMB / 32, BATCH), 256>>>(qkv, kt);

    // 3) scores[b] = Q[b] @ Kt[b] * 1/32   (M=2048, N=2048, K=1024)
    hmma_gemm<<<dim3(SEQ / 128, SEQ / 128, BATCH), 256, DSMEM>>>(
        qkv, 3 * EMB, (long)SEQ * 3 * EMB,
        kt, SEQ, (long)EMB * SEQ,
        scores, SEQ, (long)SEQ * SEQ,
        EMB, 1.0f / 32.0f);

    // 4) softmax rows
    softmax_kernel<<<BATCH * SEQ, 256>>>(scores);

    // 5) out[b] = P[b] @ V[b]   (M=2048, N=1024, K=2048)
    hmma_gemm<<<dim3(EMB / 128, SEQ / 128, BATCH), 256, DSMEM>>>(
        scores, SEQ, (long)SEQ * SEQ,
        qkv + 2 * EMB, 3 * EMB, (long)SEQ * 3 * EMB,
        out, EMB, (long)SEQ * EMB,
        SEQ, 1.0f);
}